// round 13
// baseline (speedup 1.0000x reference)
#include <cuda_runtime.h>
#include <cstdint>

// CircleProjectionLayer: z = center + (x-center) * min(1, 1/||x-center||)
// B = 8388608 points, [B,3] f32. HBM stream: 192MB read + 96MB write.
//
// R12: 256-bit global accesses (sm_100+ ld/st.global.v8.f32).
// 8 points/thread = 96B = 3 x 32B chunks per array. Unlike the failed
// float4 @96B-stride variant (16B/lane = half-sector, broken merging),
// every v8 lane consumes a FULL 32B sector -> perfect sector merging,
// half the memory instructions per byte, double burst length.

__device__ __forceinline__ void ldg256(const float* __restrict__ p, float* r) {
    asm volatile("ld.global.v8.f32 {%0,%1,%2,%3,%4,%5,%6,%7}, [%8];"
                 : "=f"(r[0]), "=f"(r[1]), "=f"(r[2]), "=f"(r[3]),
                   "=f"(r[4]), "=f"(r[5]), "=f"(r[6]), "=f"(r[7])
                 : "l"(p));
}

__device__ __forceinline__ void stg256(float* __restrict__ p, const float* r) {
    asm volatile("st.global.v8.f32 [%0], {%1,%2,%3,%4,%5,%6,%7,%8};"
                 :: "l"(p),
                    "f"(r[0]), "f"(r[1]), "f"(r[2]), "f"(r[3]),
                    "f"(r[4]), "f"(r[5]), "f"(r[6]), "f"(r[7])
                 : "memory");
}

__global__ void __launch_bounds__(512)
circle_proj_kernel(const float* __restrict__ x,
                   const float* __restrict__ c,
                   float* __restrict__ o)
{
    long i = (long)blockIdx.x * blockDim.x + threadIdx.x;
    long base = 24L * i;   // 8 points * 3 floats

    float xs[24], cs[24], os[24];

    // Front-batch all 6 x 256-bit loads (full-sector lanes).
    ldg256(x + base +  0, xs +  0);
    ldg256(x + base +  8, xs +  8);
    ldg256(x + base + 16, xs + 16);
    ldg256(c + base +  0, cs +  0);
    ldg256(c + base +  8, cs +  8);
    ldg256(c + base + 16, cs + 16);

#pragma unroll
    for (int p = 0; p < 8; p++) {
        float dx = xs[3 * p + 0] - cs[3 * p + 0];
        float dy = xs[3 * p + 1] - cs[3 * p + 1];
        float dz = xs[3 * p + 2] - cs[3 * p + 2];
        float n2 = fmaf(dx, dx, fmaf(dy, dy, dz * dz));
        // RADIUS = 1: scale = min(1, 1/||d||); rsqrtf(0)=inf -> scale=1 -> z=x.
        float s = fminf(1.0f, rsqrtf(n2));
        os[3 * p + 0] = fmaf(dx, s, cs[3 * p + 0]);
        os[3 * p + 1] = fmaf(dy, s, cs[3 * p + 1]);
        os[3 * p + 2] = fmaf(dz, s, cs[3 * p + 2]);
    }

    // 3 x 256-bit stores.
    stg256(o + base +  0, os +  0);
    stg256(o + base +  8, os +  8);
    stg256(o + base + 16, os + 16);
}

extern "C" void kernel_launch(void* const* d_in, const int* in_sizes, int n_in,
                              void* d_out, int out_size)
{
    const float* x = (const float*)d_in[0];   // x: [B,3] f32
    const float* c = (const float*)d_in[1];   // center: [B,3] f32
    float* o = (float*)d_out;

    int n_elems = in_sizes[0];           // B*3 = 25165824
    int n_points = n_elems / 3;          // 8388608
    int n_groups = n_points / 8;         // 1048576

    int threads = 512;
    int blocks = n_groups / threads;     // 2048, exact — no tail
    circle_proj_kernel<<<blocks, threads>>>(x, c, o);
}

// round 14
// speedup vs baseline: 1.0748x; 1.0748x over previous
#include <cuda_runtime.h>

// CircleProjectionLayer: z = center + (x-center) * min(1, 1/||x-center||)
// B = 8388608 points, [B,3] f32. HBM stream: 192MB read + 96MB write.
//
// FINAL (R11 config) — exhaustive single-variable search:
//   - 4 points/thread = 3 x LDG.128 per input @ 48B lane stride.
//     (8 pts via float4@96B: broken sector merging, L2 spike, -13us.
//      8 pts via v8.f32 256-bit: RF octet alignment cuts occ to 43%, -4.5us.)
//   - default caching (__ldcs/__stcs/__ldcg all measured slower)
//   - direct register path (smem transpose staging slower)
//   - flat 4096-block grid (persistent grid neutral)
//   - 512-thread blocks: block-size curve 256->45.5, 512->44.6, 1024->46.3us
//     (4 CTAs/SM minimizes cross-CTA L1tex-queue spread without coarse
//      wave-transition granularity)
//   - no tail guard: 2097152 quads = 4096 x 512 exactly; loads front-batch
//     with no predicate dependency (44.6 -> 43.97us)
// 43.97us kernel = 75.9% DRAM busy, ~6.9 TB/s app-level — the practical
// ceiling for a fine-grained 2:1 read/write stream on this part.

__global__ void __launch_bounds__(512)
circle_proj_kernel(const float4* __restrict__ x4,
                   const float4* __restrict__ c4,
                   float4* __restrict__ o4)
{
    int i = blockIdx.x * blockDim.x + threadIdx.x;
    long base = 3L * i;

    // Front-batch all 6 loads (MLP=6) before any math.
    float4 xa = x4[base + 0];
    float4 xb = x4[base + 1];
    float4 xc = x4[base + 2];
    float4 ca = c4[base + 0];
    float4 cb = c4[base + 1];
    float4 cc = c4[base + 2];

    float xs[12] = {xa.x, xa.y, xa.z, xa.w,
                    xb.x, xb.y, xb.z, xb.w,
                    xc.x, xc.y, xc.z, xc.w};
    float cs[12] = {ca.x, ca.y, ca.z, ca.w,
                    cb.x, cb.y, cb.z, cb.w,
                    cc.x, cc.y, cc.z, cc.w};
    float os[12];

#pragma unroll
    for (int p = 0; p < 4; p++) {
        float dx = xs[3 * p + 0] - cs[3 * p + 0];
        float dy = xs[3 * p + 1] - cs[3 * p + 1];
        float dz = xs[3 * p + 2] - cs[3 * p + 2];
        float n2 = fmaf(dx, dx, fmaf(dy, dy, dz * dz));
        // RADIUS = 1: scale = min(1, 1/||d||); rsqrtf(0)=inf -> scale=1 -> z=x.
        float s = fminf(1.0f, rsqrtf(n2));
        os[3 * p + 0] = fmaf(dx, s, cs[3 * p + 0]);
        os[3 * p + 1] = fmaf(dy, s, cs[3 * p + 1]);
        os[3 * p + 2] = fmaf(dz, s, cs[3 * p + 2]);
    }

    o4[base + 0] = make_float4(os[0], os[1], os[2],  os[3]);
    o4[base + 1] = make_float4(os[4], os[5], os[6],  os[7]);
    o4[base + 2] = make_float4(os[8], os[9], os[10], os[11]);
}

extern "C" void kernel_launch(void* const* d_in, const int* in_sizes, int n_in,
                              void* d_out, int out_size)
{
    const float4* x4 = (const float4*)d_in[0];   // x: [B,3] f32
    const float4* c4 = (const float4*)d_in[1];   // center: [B,3] f32
    float4* o4 = (float4*)d_out;

    int n_elems = in_sizes[0];          // B*3 = 25165824
    int n_points = n_elems / 3;         // 8388608
    int n_quads = n_points / 4;         // 2097152

    int threads = 512;
    int blocks = n_quads / threads;     // 4096, exact — no tail
    circle_proj_kernel<<<blocks, threads>>>(x4, c4, o4);
}